// round 16
// baseline (speedup 1.0000x reference)
#include <cuda_runtime.h>
#include <cuda_fp16.h>
#include <cstdint>
#include <cstddef>

// Sizes: hidden (2,4096,2048) f32; Win (6144,2048); conv_w (2048,1,3); Wout (2048,2048)
#define MDIM 8192
#define KDIM 2048
#define N1   6144
#define SEQMASK 4095
#define KT 32

// ---------------- device scratch ----------------
__device__ __half g_A  [MDIM * KDIM];          // 32 MB
__device__ __half g_W1 [N1   * KDIM];          // 24 MB
__device__ __half g_W2 [KDIM * KDIM];          // 8 MB
__device__ __half g_y  [MDIM * KDIM];          // 32 MB
__device__ __half g_BCx[(size_t)MDIM * N1];    // 96 MB fp16 GEMM1 output

// ---------------- helpers ----------------
__device__ __forceinline__ uint32_t smem_u32(const void* p) {
    uint32_t a;
    asm("{ .reg .u64 t; cvta.to.shared.u64 t, %1; cvt.u32.u64 %0, t; }" : "=r"(a) : "l"(p));
    return a;
}
__device__ __forceinline__ void cp16(uint32_t dst, const void* src) {
    asm volatile("cp.async.cg.shared.global [%0], [%1], 16;" :: "r"(dst), "l"(src));
}
__device__ __forceinline__ void ldsm_x4(uint32_t& r0, uint32_t& r1, uint32_t& r2, uint32_t& r3, uint32_t addr) {
    asm volatile("ldmatrix.sync.aligned.m8n8.x4.shared.b16 {%0,%1,%2,%3}, [%4];"
                 : "=r"(r0), "=r"(r1), "=r"(r2), "=r"(r3) : "r"(addr));
}
__device__ __forceinline__ void ldsm_x2(uint32_t& r0, uint32_t& r1, uint32_t addr) {
    asm volatile("ldmatrix.sync.aligned.m8n8.x2.shared.b16 {%0,%1}, [%2];"
                 : "=r"(r0), "=r"(r1) : "r"(addr));
}
__device__ __forceinline__ void mma16816(float* d, const uint32_t* a, const uint32_t* b) {
    asm volatile(
        "mma.sync.aligned.m16n8k16.row.col.f32.f16.f16.f32 "
        "{%0,%1,%2,%3}, {%4,%5,%6,%7}, {%8,%9}, {%0,%1,%2,%3};"
        : "+f"(d[0]), "+f"(d[1]), "+f"(d[2]), "+f"(d[3])
        : "r"(a[0]), "r"(a[1]), "r"(a[2]), "r"(a[3]), "r"(b[0]), "r"(b[1]));
}

#define SWZ(o) ((o) ^ (((o) >> 3) & 0x70))

// ---------------- f32 -> f16 convert ----------------
__global__ void __launch_bounds__(256) convert_kernel(const float4* __restrict__ src,
                                                      uint2* __restrict__ dst) {
    int i = blockIdx.x * 256 + threadIdx.x;
    float4 v = src[i];
    __half2 a = __floats2half2_rn(v.x, v.y);
    __half2 b = __floats2half2_rn(v.z, v.w);
    uint2 u;
    u.x = *reinterpret_cast<unsigned*>(&a);
    u.y = *reinterpret_cast<unsigned*>(&b);
    dst[i] = u;
}

// ---------------- TN fp16 GEMM: 5-stage ring, spread cp.async, one barrier/tile ------
// BM=BN=128, BK=64 halfs (128B SW128 rows), 256 threads (8 warps 2m x 4n,
// warp tile 64x32), double-buffered ldmatrix fragments.
// Prefetch slot (kt+4)%5 is disjoint from read slot kt%5, so gmem loads are
// issued in quarters between MMA steps (no burst) and the tile boundary is a
// single commit -> wait_group 3 -> __syncthreads -> frag preload.
#define STAGE_BYTES 32768          // A 16KB + B 16KB
#define GSMEM (5 * STAGE_BYTES)    // 163840

template <typename OutT>
__global__ void __launch_bounds__(256, 1) hgemm_tn(const __half* __restrict__ A,
                                                   const __half* __restrict__ W,
                                                   OutT* __restrict__ C, int ldc) {
    extern __shared__ char smem[];
    const int t = threadIdx.x;
    const int tm = blockIdx.y * 128;
    const int tn = blockIdx.x * 128;
    const uint32_t sb = smem_u32(smem);

    auto load_quarter = [&](int st, int kt, int p) {
        const uint32_t sa = sb + st * STAGE_BYTES;
        const __half* Ag = A + (size_t)tm * KDIM + kt * 64;
        const __half* Wg = W + (size_t)tn * KDIM + kt * 64;
        int id = p * 256 + t;
        int r = id >> 3, c = id & 7;
        cp16(sa + SWZ(r * 128 + c * 16), Ag + (size_t)r * KDIM + c * 8);
        cp16(sa + 16384 + SWZ(r * 128 + c * 16), Wg + (size_t)r * KDIM + c * 8);
    };
    auto load_stage = [&](int st, int kt) {
        #pragma unroll
        for (int p = 0; p < 4; p++) load_quarter(st, kt, p);
    };

    load_stage(0, 0); asm volatile("cp.async.commit_group;" ::: "memory");
    load_stage(1, 1); asm volatile("cp.async.commit_group;" ::: "memory");
    load_stage(2, 2); asm volatile("cp.async.commit_group;" ::: "memory");
    load_stage(3, 3); asm volatile("cp.async.commit_group;" ::: "memory");

    const int warp = t >> 5, lane = t & 31;
    const int wm = (warp >> 2) * 64;
    const int wn = (warp & 3) * 32;
    const int g = lane >> 3;
    const int a_row = (g & 1) * 8 + (lane & 7);
    const int a_kb  = (g >> 1) * 16;
    const int lg = lane & 15;
    const int b_row = lg & 7;
    const int b_kb  = (lg >> 3) * 16;

    const int axor = (a_row & 7) << 4;
    const int bxor = (b_row & 7) << 4;
    int rowA[4], rowB[4];
    #pragma unroll
    for (int mt = 0; mt < 4; mt++) rowA[mt] = (wm + mt * 16 + a_row) * 128;
    #pragma unroll
    for (int nt = 0; nt < 4; nt++) rowB[nt] = (wn + nt * 8 + b_row) * 128 + 16384;

    float acc[16][4] = {};
    uint32_t fa0[4][4], fa1[4][4], fb0[4][2], fb1[4][2];

#define LOAD_FRAGS(FA, FB, base, ksv)                                             \
    {                                                                             \
        const int ca = (((ksv) * 32 + a_kb) ^ axor);                              \
        const int cb = (((ksv) * 32 + b_kb) ^ bxor);                              \
        _Pragma("unroll")                                                         \
        for (int mt = 0; mt < 4; mt++)                                            \
            ldsm_x4(FA[mt][0], FA[mt][1], FA[mt][2], FA[mt][3], (base) + rowA[mt] + ca); \
        _Pragma("unroll")                                                         \
        for (int nt = 0; nt < 4; nt++)                                            \
            ldsm_x2(FB[nt][0], FB[nt][1], (base) + rowB[nt] + cb);                \
    }

#define MMA_STEP(FA, FB)                                                          \
    {                                                                             \
        _Pragma("unroll")                                                         \
        for (int mt = 0; mt < 4; mt++)                                            \
            _Pragma("unroll")                                                     \
            for (int nt = 0; nt < 4; nt++)                                        \
                mma16816(acc[mt * 4 + nt], FA[mt], FB[nt]);                       \
    }

    // prologue: stage 0 landed + visible, preload first fragments
    asm volatile("cp.async.wait_group 3;" ::: "memory");
    __syncthreads();
    LOAD_FRAGS(fa0, fb0, sb, 0);

    for (int kt = 0; kt < KT; kt++) {
        const uint32_t sc = sb + (kt % 5) * STAGE_BYTES;
        const bool pre = (kt + 4 < KT);
        const int slot = (kt + 4) % 5;        // == (kt-1)%5, protected by iter kt-1's barrier

        LOAD_FRAGS(fa1, fb1, sc, 1);
        if (pre) load_quarter(slot, kt + 4, 0);
        MMA_STEP(fa0, fb0);
        LOAD_FRAGS(fa0, fb0, sc, 2);
        if (pre) load_quarter(slot, kt + 4, 1);
        MMA_STEP(fa1, fb1);
        LOAD_FRAGS(fa1, fb1, sc, 3);
        if (pre) load_quarter(slot, kt + 4, 2);
        MMA_STEP(fa0, fb0);
        if (pre) load_quarter(slot, kt + 4, 3);
        asm volatile("cp.async.commit_group;" ::: "memory");
        MMA_STEP(fa1, fb1);

        // single boundary: stage kt+1 landed, visible to all, slot kt%5 released
        asm volatile("cp.async.wait_group 3;" ::: "memory");
        __syncthreads();
        if (kt + 1 < KT) {
            const uint32_t sn = sb + ((kt + 1) % 5) * STAGE_BYTES;
            LOAD_FRAGS(fa0, fb0, sn, 0);
        }
    }

    // epilogue
    #pragma unroll
    for (int mt = 0; mt < 4; mt++) {
        #pragma unroll
        for (int nt = 0; nt < 4; nt++) {
            const float* d = acc[mt * 4 + nt];
            int row = tm + wm + mt * 16 + (lane >> 2);
            int col = tn + wn + nt * 8 + (lane & 3) * 2;
            if constexpr (sizeof(OutT) == 2) {
                *reinterpret_cast<__half2*>((__half*)C + (size_t)row * ldc + col)
                    = __floats2half2_rn(d[0], d[1]);
                *reinterpret_cast<__half2*>((__half*)C + (size_t)(row + 8) * ldc + col)
                    = __floats2half2_rn(d[2], d[3]);
            } else {
                *reinterpret_cast<float2*>((float*)C + (size_t)row * ldc + col)
                    = make_float2(d[0], d[1]);
                *reinterpret_cast<float2*>((float*)C + (size_t)(row + 8) * ldc + col)
                    = make_float2(d[2], d[3]);
            }
        }
    }
#undef LOAD_FRAGS
#undef MMA_STEP
}

// ---------------- fused B*x -> causal conv(L=3) -> *C, fp16 in / fp16 out (R8-exact) -
__global__ void __launch_bounds__(256) shortconv_kernel(const __half* __restrict__ BCx,
                                                        const float* __restrict__ cw,
                                                        __half* __restrict__ y) {
    int gid = blockIdx.x * 256 + threadIdx.x;  // 8192 * 512 threads
    int m = gid >> 9;
    int h = (gid & 511) * 4;
    int s = m & SEQMASK;

    const __half* row0 = BCx + (size_t)m * N1;
    auto ld4 = [](const __half* p, float* out) {
        uint2 u = *reinterpret_cast<const uint2*>(p);
        float2 lo = __half22float2(*reinterpret_cast<__half2*>(&u.x));
        float2 hi = __half22float2(*reinterpret_cast<__half2*>(&u.y));
        out[0] = lo.x; out[1] = lo.y; out[2] = hi.x; out[3] = hi.y;
    };

    float b0[4], cc[4], x0[4];
    float b1[4] = {0,0,0,0}, x1[4] = {0,0,0,0}, b2[4] = {0,0,0,0}, x2[4] = {0,0,0,0};
    ld4(row0 + h, b0);
    ld4(row0 + 2048 + h, cc);
    ld4(row0 + 4096 + h, x0);
    if (s >= 1) { ld4(row0 - N1 + h, b1); ld4(row0 - N1 + 4096 + h, x1); }
    if (s >= 2) { ld4(row0 - 2 * N1 + h, b2); ld4(row0 - 2 * N1 + 4096 + h, x2); }

    float out[4];
    #pragma unroll
    for (int j = 0; j < 4; j++) {
        float w0 = cw[(h + j) * 3 + 0];
        float w1 = cw[(h + j) * 3 + 1];
        float w2 = cw[(h + j) * 3 + 2];
        out[j] = cc[j] * (w0 * b2[j] * x2[j] + w1 * b1[j] * x1[j] + w2 * b0[j] * x0[j]);
    }
    *reinterpret_cast<__half2*>(y + (size_t)m * KDIM + h)     = __floats2half2_rn(out[0], out[1]);
    *reinterpret_cast<__half2*>(y + (size_t)m * KDIM + h + 2) = __floats2half2_rn(out[2], out[3]);
}

// ---------------- launch ----------------
extern "C" void kernel_launch(void* const* d_in, const int* in_sizes, int n_in,
                              void* d_out, int out_size) {
    const float* hs   = (const float*)d_in[0];
    const float* Win  = (const float*)d_in[1];
    const float* cw   = (const float*)d_in[2];
    const float* Wout = (const float*)d_in[3];
    float* out = (float*)d_out;

    void *pA, *pW1, *pW2, *pY, *pBCx;
    cudaGetSymbolAddress(&pA,  g_A);
    cudaGetSymbolAddress(&pW1, g_W1);
    cudaGetSymbolAddress(&pW2, g_W2);
    cudaGetSymbolAddress(&pY,  g_y);
    cudaGetSymbolAddress(&pBCx, g_BCx);

    cudaFuncSetAttribute(hgemm_tn<__half>, cudaFuncAttributeMaxDynamicSharedMemorySize, GSMEM);
    cudaFuncSetAttribute(hgemm_tn<float>,  cudaFuncAttributeMaxDynamicSharedMemorySize, GSMEM);

    convert_kernel<<<16384, 256>>>((const float4*)hs,   (uint2*)pA);
    convert_kernel<<<12288, 256>>>((const float4*)Win,  (uint2*)pW1);
    convert_kernel<<<4096,  256>>>((const float4*)Wout, (uint2*)pW2);

    // GEMM1: BCx[8192,6144] (fp16) = A * Win^T
    hgemm_tn<__half><<<dim3(N1 / 128, MDIM / 128), 256, GSMEM>>>(
        (const __half*)pA, (const __half*)pW1, (__half*)pBCx, N1);

    shortconv_kernel<<<(MDIM * KDIM / 4) / 256, 256>>>((const __half*)pBCx, cw, (__half*)pY);

    // GEMM2: out[8192,2048] (fp32) = y * Wout^T
    hgemm_tn<float><<<dim3(KDIM / 128, MDIM / 128), 256, GSMEM>>>(
        (const __half*)pY, (const __half*)pW2, out, KDIM);
}

// round 17
// speedup vs baseline: 1.1064x; 1.1064x over previous
#include <cuda_runtime.h>
#include <cuda_fp16.h>
#include <cstdint>
#include <cstddef>

// Sizes: hidden (2,4096,2048) f32; Win (6144,2048); conv_w (2048,1,3); Wout (2048,2048)
#define MDIM 8192
#define KDIM 2048
#define N1   6144
#define SEQMASK 4095
#define KT 32

// ---------------- device scratch ----------------
__device__ __half g_A  [MDIM * KDIM];          // 32 MB
__device__ __half g_W1 [N1   * KDIM];          // 24 MB
__device__ __half g_W2 [KDIM * KDIM];          // 8 MB
__device__ __half g_y  [MDIM * KDIM];          // 32 MB
__device__ __half g_BCx[(size_t)MDIM * N1];    // 96 MB fp16 GEMM1 output

// ---------------- helpers ----------------
__device__ __forceinline__ uint32_t smem_u32(const void* p) {
    uint32_t a;
    asm("{ .reg .u64 t; cvta.to.shared.u64 t, %1; cvt.u32.u64 %0, t; }" : "=r"(a) : "l"(p));
    return a;
}
__device__ __forceinline__ void cp16(uint32_t dst, const void* src) {
    asm volatile("cp.async.cg.shared.global [%0], [%1], 16;" :: "r"(dst), "l"(src));
}
__device__ __forceinline__ void ldsm_x4(uint32_t& r0, uint32_t& r1, uint32_t& r2, uint32_t& r3, uint32_t addr) {
    asm volatile("ldmatrix.sync.aligned.m8n8.x4.shared.b16 {%0,%1,%2,%3}, [%4];"
                 : "=r"(r0), "=r"(r1), "=r"(r2), "=r"(r3) : "r"(addr));
}
__device__ __forceinline__ void ldsm_x2(uint32_t& r0, uint32_t& r1, uint32_t addr) {
    asm volatile("ldmatrix.sync.aligned.m8n8.x2.shared.b16 {%0,%1}, [%2];"
                 : "=r"(r0), "=r"(r1) : "r"(addr));
}
__device__ __forceinline__ void mma16816(float* d, const uint32_t* a, const uint32_t* b) {
    asm volatile(
        "mma.sync.aligned.m16n8k16.row.col.f32.f16.f16.f32 "
        "{%0,%1,%2,%3}, {%4,%5,%6,%7}, {%8,%9}, {%0,%1,%2,%3};"
        : "+f"(d[0]), "+f"(d[1]), "+f"(d[2]), "+f"(d[3])
        : "r"(a[0]), "r"(a[1]), "r"(a[2]), "r"(a[3]), "r"(b[0]), "r"(b[1]));
}

#define SWZ(o) ((o) ^ (((o) >> 3) & 0x70))

// ---------------- f32 -> f16 convert ----------------
__global__ void __launch_bounds__(256) convert_kernel(const float4* __restrict__ src,
                                                      uint2* __restrict__ dst) {
    int i = blockIdx.x * 256 + threadIdx.x;
    float4 v = src[i];
    __half2 a = __floats2half2_rn(v.x, v.y);
    __half2 b = __floats2half2_rn(v.z, v.w);
    uint2 u;
    u.x = *reinterpret_cast<unsigned*>(&a);
    u.y = *reinterpret_cast<unsigned*>(&b);
    dst[i] = u;
}

// ---------------- TN fp16 GEMM (R8-exact, best-measured: 77% tensor, 442.5us) --------
// BM=BN=128, BK=64 halfs (128B SW128 rows), 4-stage cp.async ring, 256 threads
// (8 warps 2m x 4n, warp tile 64x32), double-buffered ldmatrix fragments.
#define STAGE_BYTES 32768          // A 16KB + B 16KB
#define GSMEM (4 * STAGE_BYTES)    // 131072

template <typename OutT>
__global__ void __launch_bounds__(256, 1) hgemm_tn(const __half* __restrict__ A,
                                                   const __half* __restrict__ W,
                                                   OutT* __restrict__ C, int ldc) {
    extern __shared__ char smem[];
    const int t = threadIdx.x;
    const int tm = blockIdx.y * 128;
    const int tn = blockIdx.x * 128;
    const uint32_t sb = smem_u32(smem);

    auto load_stage = [&](int st, int kt) {
        const uint32_t sa = sb + st * STAGE_BYTES;
        const __half* Ag = A + (size_t)tm * KDIM + kt * 64;
        const __half* Wg = W + (size_t)tn * KDIM + kt * 64;
        #pragma unroll
        for (int p = 0; p < 4; p++) {
            int id = p * 256 + t;
            int r = id >> 3, c = id & 7;
            cp16(sa + SWZ(r * 128 + c * 16), Ag + (size_t)r * KDIM + c * 8);
            cp16(sa + 16384 + SWZ(r * 128 + c * 16), Wg + (size_t)r * KDIM + c * 8);
        }
    };

    load_stage(0, 0); asm volatile("cp.async.commit_group;" ::: "memory");
    load_stage(1, 1); asm volatile("cp.async.commit_group;" ::: "memory");
    load_stage(2, 2); asm volatile("cp.async.commit_group;" ::: "memory");
    load_stage(3, 3); asm volatile("cp.async.commit_group;" ::: "memory");

    const int warp = t >> 5, lane = t & 31;
    const int wm = (warp >> 2) * 64;
    const int wn = (warp & 3) * 32;
    const int g = lane >> 3;
    const int a_row = (g & 1) * 8 + (lane & 7);
    const int a_kb  = (g >> 1) * 16;
    const int lg = lane & 15;
    const int b_row = lg & 7;
    const int b_kb  = (lg >> 3) * 16;

    const int axor = (a_row & 7) << 4;
    const int bxor = (b_row & 7) << 4;
    int rowA[4], rowB[4];
    #pragma unroll
    for (int mt = 0; mt < 4; mt++) rowA[mt] = (wm + mt * 16 + a_row) * 128;
    #pragma unroll
    for (int nt = 0; nt < 4; nt++) rowB[nt] = (wn + nt * 8 + b_row) * 128 + 16384;

    float acc[16][4] = {};
    uint32_t fa0[4][4], fa1[4][4], fb0[4][2], fb1[4][2];

#define LOAD_FRAGS(FA, FB, base, ksv)                                             \
    {                                                                             \
        const int ca = (((ksv) * 32 + a_kb) ^ axor);                              \
        const int cb = (((ksv) * 32 + b_kb) ^ bxor);                              \
        _Pragma("unroll")                                                         \
        for (int mt = 0; mt < 4; mt++)                                            \
            ldsm_x4(FA[mt][0], FA[mt][1], FA[mt][2], FA[mt][3], (base) + rowA[mt] + ca); \
        _Pragma("unroll")                                                         \
        for (int nt = 0; nt < 4; nt++)                                            \
            ldsm_x2(FB[nt][0], FB[nt][1], (base) + rowB[nt] + cb);                \
    }

#define MMA_STEP(FA, FB)                                                          \
    {                                                                             \
        _Pragma("unroll")                                                         \
        for (int mt = 0; mt < 4; mt++)                                            \
            _Pragma("unroll")                                                     \
            for (int nt = 0; nt < 4; nt++)                                        \
                mma16816(acc[mt * 4 + nt], FA[mt], FB[nt]);                       \
    }

    asm volatile("cp.async.wait_group 3;" ::: "memory");
    __syncthreads();
    LOAD_FRAGS(fa0, fb0, sb, 0);

    for (int kt = 0; kt < KT; kt++) {
        const uint32_t sc = sb + (kt & 3) * STAGE_BYTES;
        LOAD_FRAGS(fa1, fb1, sc, 1);
        MMA_STEP(fa0, fb0);
        LOAD_FRAGS(fa0, fb0, sc, 2);
        MMA_STEP(fa1, fb1);
        LOAD_FRAGS(fa1, fb1, sc, 3);
        MMA_STEP(fa0, fb0);
        MMA_STEP(fa1, fb1);

        __syncthreads();                       // all warps done reading slot kt&3
        if (kt + 4 < KT) load_stage(kt & 3, kt + 4);
        asm volatile("cp.async.commit_group;" ::: "memory");
        asm volatile("cp.async.wait_group 3;" ::: "memory");
        __syncthreads();                       // stage kt+1 visible
        if (kt + 1 < KT) {
            const uint32_t sn = sb + ((kt + 1) & 3) * STAGE_BYTES;
            LOAD_FRAGS(fa0, fb0, sn, 0);
        }
    }

    // epilogue
    #pragma unroll
    for (int mt = 0; mt < 4; mt++) {
        #pragma unroll
        for (int nt = 0; nt < 4; nt++) {
            const float* d = acc[mt * 4 + nt];
            int row = tm + wm + mt * 16 + (lane >> 2);
            int col = tn + wn + nt * 8 + (lane & 3) * 2;
            if constexpr (sizeof(OutT) == 2) {
                *reinterpret_cast<__half2*>((__half*)C + (size_t)row * ldc + col)
                    = __floats2half2_rn(d[0], d[1]);
                *reinterpret_cast<__half2*>((__half*)C + (size_t)(row + 8) * ldc + col)
                    = __floats2half2_rn(d[2], d[3]);
            } else {
                *reinterpret_cast<float2*>((float*)C + (size_t)row * ldc + col)
                    = make_float2(d[0], d[1]);
                *reinterpret_cast<float2*>((float*)C + (size_t)(row + 8) * ldc + col)
                    = make_float2(d[2], d[3]);
            }
        }
    }
#undef LOAD_FRAGS
#undef MMA_STEP
}

// ---------------- fused B*x -> causal conv(L=3) -> *C, fp16 in / fp16 out ------------
__global__ void __launch_bounds__(256) shortconv_kernel(const __half* __restrict__ BCx,
                                                        const float* __restrict__ cw,
                                                        __half* __restrict__ y) {
    int gid = blockIdx.x * 256 + threadIdx.x;  // 8192 * 512 threads
    int m = gid >> 9;
    int h = (gid & 511) * 4;
    int s = m & SEQMASK;

    const __half* row0 = BCx + (size_t)m * N1;
    auto ld4 = [](const __half* p, float* out) {
        uint2 u = *reinterpret_cast<const uint2*>(p);
        float2 lo = __half22float2(*reinterpret_cast<__half2*>(&u.x));
        float2 hi = __half22float2(*reinterpret_cast<__half2*>(&u.y));
        out[0] = lo.x; out[1] = lo.y; out[2] = hi.x; out[3] = hi.y;
    };

    float b0[4], cc[4], x0[4];
    float b1[4] = {0,0,0,0}, x1[4] = {0,0,0,0}, b2[4] = {0,0,0,0}, x2[4] = {0,0,0,0};
    ld4(row0 + h, b0);
    ld4(row0 + 2048 + h, cc);
    ld4(row0 + 4096 + h, x0);
    if (s >= 1) { ld4(row0 - N1 + h, b1); ld4(row0 - N1 + 4096 + h, x1); }
    if (s >= 2) { ld4(row0 - 2 * N1 + h, b2); ld4(row0 - 2 * N1 + 4096 + h, x2); }

    float out[4];
    #pragma unroll
    for (int j = 0; j < 4; j++) {
        float w0 = cw[(h + j) * 3 + 0];
        float w1 = cw[(h + j) * 3 + 1];
        float w2 = cw[(h + j) * 3 + 2];
        out[j] = cc[j] * (w0 * b2[j] * x2[j] + w1 * b1[j] * x1[j] + w2 * b0[j] * x0[j]);
    }
    *reinterpret_cast<__half2*>(y + (size_t)m * KDIM + h)     = __floats2half2_rn(out[0], out[1]);
    *reinterpret_cast<__half2*>(y + (size_t)m * KDIM + h + 2) = __floats2half2_rn(out[2], out[3]);
}

// ---------------- launch ----------------
extern "C" void kernel_launch(void* const* d_in, const int* in_sizes, int n_in,
                              void* d_out, int out_size) {
    const float* hs   = (const float*)d_in[0];
    const float* Win  = (const float*)d_in[1];
    const float* cw   = (const float*)d_in[2];
    const float* Wout = (const float*)d_in[3];
    float* out = (float*)d_out;

    void *pA, *pW1, *pW2, *pY, *pBCx;
    cudaGetSymbolAddress(&pA,  g_A);
    cudaGetSymbolAddress(&pW1, g_W1);
    cudaGetSymbolAddress(&pW2, g_W2);
    cudaGetSymbolAddress(&pY,  g_y);
    cudaGetSymbolAddress(&pBCx, g_BCx);

    cudaFuncSetAttribute(hgemm_tn<__half>, cudaFuncAttributeMaxDynamicSharedMemorySize, GSMEM);
    cudaFuncSetAttribute(hgemm_tn<float>,  cudaFuncAttributeMaxDynamicSharedMemorySize, GSMEM);

    convert_kernel<<<16384, 256>>>((const float4*)hs,   (uint2*)pA);
    convert_kernel<<<12288, 256>>>((const float4*)Win,  (uint2*)pW1);
    convert_kernel<<<4096,  256>>>((const float4*)Wout, (uint2*)pW2);

    // GEMM1: BCx[8192,6144] (fp16) = A * Win^T
    hgemm_tn<__half><<<dim3(N1 / 128, MDIM / 128), 256, GSMEM>>>(
        (const __half*)pA, (const __half*)pW1, (__half*)pBCx, N1);

    shortconv_kernel<<<(MDIM * KDIM / 4) / 256, 256>>>((const __half*)pBCx, cw, (__half*)pY);

    // GEMM2: out[8192,2048] (fp32) = y * Wout^T
    hgemm_tn<float><<<dim3(KDIM / 128, MDIM / 128), 256, GSMEM>>>(
        (const __half*)pY, (const __half*)pW2, out, KDIM);
}